// round 1
// baseline (speedup 1.0000x reference)
#include <cuda_runtime.h>

#define NBATCH 4
#define NCH 3
#define HH 128
#define WW 128
#define HW 16384
#define NN 65536
#define HID 128
#define NL 6
#define NPRM 5
#define EPSV 1e-5f
#define DTV 0.1f

// ---------------- scratch (device globals; no allocation) ----------------
__device__ float g_f[(size_t)NN * HID];
__device__ float g_A[(size_t)NN * HID];
__device__ float g_Bm[(size_t)NN * HID];
__device__ float g_tmp[(size_t)NN * HID];
__device__ float g_stats[NBATCH * 2 * HID];

__constant__ int c_dr[8] = {-1, -1, -1, 0, 0, 1, 1, 1};
__constant__ int c_dc[8] = {-1, 0, 1, -1, 1, -1, 0, 1};

__device__ __forceinline__ float swishf(float x) {
    return x / (1.0f + __expf(-x));
}

#define ACC_ZERO(acc)                                                  \
    _Pragma("unroll") for (int _i = 0; _i < 4; ++_i)                   \
        _Pragma("unroll") for (int _j = 0; _j < 8; ++_j) acc[_i][_j] = 0.0f;

// 4x8 register-tile GEMM over K=128. A is smem [rows][lda], W is smem [128][ldw].
// Thread computes rows {tr + i*RSTEP}, cols [tc*8, tc*8+8).
template <int RSTEP>
__device__ __forceinline__ void gemm128(const float* __restrict__ As, int lda,
                                        const float* __restrict__ Ws, int ldw,
                                        float acc[4][8], int tr, int tc) {
#pragma unroll 4
    for (int k4 = 0; k4 < 32; ++k4) {
        float4 a[4];
#pragma unroll
        for (int i = 0; i < 4; ++i)
            a[i] = *(const float4*)(As + (tr + i * RSTEP) * lda + k4 * 4);
        const float* wp = Ws + (k4 * 4) * ldw + tc * 8;
#pragma unroll
        for (int kk = 0; kk < 4; ++kk) {
            float4 b0 = *(const float4*)(wp + kk * ldw);
            float4 b1 = *(const float4*)(wp + kk * ldw + 4);
#pragma unroll
            for (int i = 0; i < 4; ++i) {
                float av = ((const float*)(a + i))[kk];
                acc[i][0] = fmaf(av, b0.x, acc[i][0]);
                acc[i][1] = fmaf(av, b0.y, acc[i][1]);
                acc[i][2] = fmaf(av, b0.z, acc[i][2]);
                acc[i][3] = fmaf(av, b0.w, acc[i][3]);
                acc[i][4] = fmaf(av, b1.x, acc[i][4]);
                acc[i][5] = fmaf(av, b1.y, acc[i][5]);
                acc[i][6] = fmaf(av, b1.z, acc[i][6]);
                acc[i][7] = fmaf(av, b1.w, acc[i][7]);
            }
        }
    }
}

// ---------------- embedding: f = swish(swish(e@W1+b1)@W2+b2) ----------------
__global__ __launch_bounds__(256, 2) void k_embed(
    const float* __restrict__ inp, const float* __restrict__ cp,
    const float* __restrict__ W1, const float* __restrict__ b1,
    const float* __restrict__ W2, const float* __restrict__ b2) {
    extern __shared__ float sm[];
    float* e_s = sm;                  // 64*8
    float* W1_s = e_s + 64 * 8;       // 8*128
    float* b1_s = W1_s + 8 * 128;     // 128
    float* h1_s = b1_s + 128;         // 64*132
    float* W2_s = h1_s + 64 * 132;    // 128*128
    float* b2_s = W2_s + 128 * 128;   // 128

    int tid = threadIdx.x;
    int n0 = blockIdx.x * 64;
    int b = n0 / HW;

    for (int i = tid; i < 8 * 128; i += 256) W1_s[i] = W1[i];
    if (tid < 128) { b1_s[tid] = b1[tid]; b2_s[tid] = b2[tid]; }
    for (int i = tid; i < 128 * 32; i += 256)
        ((float4*)W2_s)[i] = ((const float4*)W2)[i];
    if (tid < 64) {
        int n = n0 + tid;
        int rc = n - b * HW;
        int r = rc >> 7, c = rc & 127;
        e_s[tid * 8 + 0] = inp[b * NCH * HW + rc];
        e_s[tid * 8 + 1] = (float)r * (1.0f / 127.0f) * cp[b * NPRM + 1];
        e_s[tid * 8 + 2] = (float)c * (1.0f / 127.0f) * cp[b * NPRM + 0];
#pragma unroll
        for (int p = 0; p < NPRM; ++p) e_s[tid * 8 + 3 + p] = cp[b * NPRM + p];
    }
    __syncthreads();

    int tc = tid & 15, tr = tid >> 4;
#pragma unroll
    for (int i = 0; i < 4; ++i) {
        int row = tr + 16 * i;
#pragma unroll
        for (int j = 0; j < 8; ++j) {
            float s = b1_s[tc * 8 + j];
#pragma unroll
            for (int k = 0; k < 8; ++k)
                s = fmaf(e_s[row * 8 + k], W1_s[k * 128 + tc * 8 + j], s);
            h1_s[row * 132 + tc * 8 + j] = swishf(s);
        }
    }
    __syncthreads();
    float acc[4][8];
    ACC_ZERO(acc);
    gemm128<16>(h1_s, 132, W2_s, 128, acc, tr, tc);
#pragma unroll
    for (int i = 0; i < 4; ++i) {
        int row = tr + 16 * i;
#pragma unroll
        for (int j = 0; j < 8; ++j)
            g_f[(size_t)(n0 + row) * 128 + tc * 8 + j] =
                swishf(acc[i][j] + b2_s[tc * 8 + j]);
    }
}

// ---------------- per layer: A = f@W_t + (params@W_par + b1), Bm = f@W_s ----
__global__ __launch_bounds__(256, 2) void k_msgA(
    const float* __restrict__ cp, const float* __restrict__ msg1W,
    const float* __restrict__ msg1b, int l) {
    extern __shared__ float sm[];
    float* f_s = sm;                 // 64*132
    float* W_s = f_s + 64 * 132;     // 128*128
    float* pc_s = W_s + 128 * 128;   // 128

    int tid = threadIdx.x;
    int n0 = blockIdx.x * 64;
    int b = n0 / HW;
    const float* Wl = msg1W + (size_t)l * 264 * 128;

    if (blockIdx.x == 0)  // zero layernorm stats for this layer
        for (int i = tid; i < NBATCH * 2 * HID; i += 256) g_stats[i] = 0.0f;

    if (tid < 128) {
        float s = msg1b[l * 128 + tid];
#pragma unroll
        for (int p = 0; p < NPRM; ++p)
            s = fmaf(cp[b * NPRM + p], Wl[(259 + p) * 128 + tid], s);
        pc_s[tid] = s;
    }
    for (int i = tid; i < 64 * 32; i += 256) {
        int c = i >> 5, q = i & 31;
        ((float4*)(f_s + c * 132))[q] =
            ((const float4*)(g_f + (size_t)(n0 + c) * 128))[q];
    }
    for (int i = tid; i < 128 * 32; i += 256)
        ((float4*)W_s)[i] = ((const float4*)Wl)[i];  // rows 0..127 (W_t)
    __syncthreads();

    int tc = tid & 15, tr = tid >> 4;
    float acc[4][8];
    ACC_ZERO(acc);
    gemm128<16>(f_s, 132, W_s, 128, acc, tr, tc);
#pragma unroll
    for (int i = 0; i < 4; ++i) {
        int row = tr + 16 * i;
#pragma unroll
        for (int j = 0; j < 8; ++j)
            g_A[(size_t)(n0 + row) * 128 + tc * 8 + j] =
                acc[i][j] + pc_s[tc * 8 + j];
    }
    __syncthreads();
    for (int i = tid; i < 128 * 32; i += 256)
        ((float4*)W_s)[i] = ((const float4*)(Wl + 128 * 128))[i];  // rows 128..255 (W_s)
    __syncthreads();
    ACC_ZERO(acc);
    gemm128<16>(f_s, 132, W_s, 128, acc, tr, tc);
#pragma unroll
    for (int i = 0; i < 4; ++i) {
        int row = tr + 16 * i;
#pragma unroll
        for (int j = 0; j < 8; ++j)
            g_Bm[(size_t)(n0 + row) * 128 + tc * 8 + j] = acc[i][j];
    }
}

// ---------------- fused edge messages + aggregation + update MLP ------------
__global__ __launch_bounds__(512, 1) void k_edge(
    const float* __restrict__ inp, const float* __restrict__ cp,
    const float* __restrict__ msg1W, const float* __restrict__ msg2W,
    const float* __restrict__ msg2b, const float* __restrict__ upd1W,
    const float* __restrict__ upd1b, const float* __restrict__ upd2W,
    const float* __restrict__ upd2b, int l) {
    extern __shared__ float sm[];
    float* A_s = sm;                     // 128*132
    float* M_s = A_s + 128 * 132;        // 128*132
    float* W_s = M_s + 128 * 132;        // 128*128
    float* posW_s = W_s + 128 * 128;     // 8*128
    float* wu_s = posW_s + 8 * 128;      // 128
    float* b2m_s = wu_s + 128;           // 128
    float* pc_s = b2m_s + 128;           // 128
    float* b2u_s = pc_s + 128;           // 128
    float* du_s = b2u_s + 128;           // 128
    float* cp_s = du_s + 128;            // 8

    const int tid = threadIdx.x;
    const int gr = blockIdx.x;      // global grid row 0..511
    const int b = gr >> 7, r = gr & 127;
    const int n0 = gr << 7;         // 128 nodes = one grid row
    const float* W1l = msg1W + (size_t)l * 264 * 128;

    if (tid < 8) cp_s[tid] = (tid < NPRM) ? cp[b * NPRM + tid] : 0.0f;
    if (tid < 128) {
        wu_s[tid] = W1l[256 * 128 + tid];
        b2m_s[tid] = msg2b[l * 128 + tid];
    }
    __syncthreads();
    for (int i = tid; i < 8 * 128; i += 512) {
        int d = i >> 7, j = i & 127;
        float pdx = (float)(-c_dr[d]) * (1.0f / 127.0f) * cp_s[1];
        float pdy = (float)(-c_dc[d]) * (1.0f / 127.0f) * cp_s[0];
        posW_s[i] = pdx * W1l[257 * 128 + j] + pdy * W1l[258 * 128 + j];
    }
    for (int i = tid; i < 128 * 32; i += 512) {
        int c = i >> 5, q = i & 31;
        ((float4*)(A_s + c * 132))[q] =
            ((const float4*)(g_A + (size_t)(n0 + c) * 128))[q];
    }
    for (int i = tid; i < 128 * 32; i += 512)
        ((float4*)W_s)[i] = ((const float4*)(msg2W + (size_t)l * 128 * 128))[i];
    __syncthreads();

    const int tc = tid & 15, tr = tid >> 4;  // tr in [0,32)
    float agg[4][8];
    ACC_ZERO(agg);

    for (int d = 0; d < 8; ++d) {
        int dr = c_dr[d], dc = c_dc[d];
        if (r + dr < 0 || r + dr >= HH) continue;  // uniform per block
        __syncthreads();  // prior GEMM done reading M_s / du_s
        if (tid < 128) {
            int c = tid;
            int n = n0 + c;
            int nb = n + dr * WW + dc;
            nb = min(max(nb, 0), NN - 1);
            int bb = nb >> 14;
            du_s[c] = inp[b * NCH * HW + (n - b * HW)] -
                      inp[bb * NCH * HW + (nb - bb * HW)];
        }
        __syncthreads();
        for (int i = tid; i < 128 * 32; i += 512) {
            int c = i >> 5, q = i & 31;
            int nb = n0 + c + dr * WW + dc;
            nb = min(max(nb, 0), NN - 1);
            float4 bm = ((const float4*)(g_Bm + (size_t)nb * 128))[q];
            float4 ba = ((const float4*)(A_s + c * 132))[q];
            float du = du_s[c];
            const float* wu4 = wu_s + q * 4;
            const float* pw4 = posW_s + d * 128 + q * 4;
            float4 m;
            m.x = swishf(ba.x + bm.x + du * wu4[0] + pw4[0]);
            m.y = swishf(ba.y + bm.y + du * wu4[1] + pw4[1]);
            m.z = swishf(ba.z + bm.z + du * wu4[2] + pw4[2]);
            m.w = swishf(ba.w + bm.w + du * wu4[3] + pw4[3]);
            ((float4*)(M_s + c * 132))[q] = m;
        }
        __syncthreads();
        float acc[4][8];
        ACC_ZERO(acc);
        gemm128<32>(M_s, 132, W_s, 128, acc, tr, tc);
#pragma unroll
        for (int i = 0; i < 4; ++i) {
            int c = tr + 32 * i;
            int cc = c + dc;
            if (cc >= 0 && cc < WW) {
#pragma unroll
                for (int j = 0; j < 8; ++j)
                    agg[i][j] += swishf(acc[i][j] + b2m_s[tc * 8 + j]);
            }
        }
    }

    // -------- aggregation normalize, then update MLP --------
    __syncthreads();  // all GEMM reads of A_s/M_s/W_s done
    int cr = 1 + (r > 0) + (r < HH - 1);
#pragma unroll
    for (int i = 0; i < 4; ++i) {
        int c = tr + 32 * i;
        int ccnt = 1 + (c > 0) + (c < WW - 1);
        float inv = 1.0f / (float)(cr * ccnt - 1);
#pragma unroll
        for (int j = 0; j < 8; ++j)
            M_s[c * 132 + tc * 8 + j] = agg[i][j] * inv;  // agg tile
    }
    if (tid < 128) {
        float s = upd1b[l * 128 + tid];
#pragma unroll
        for (int p = 0; p < NPRM; ++p)
            s = fmaf(cp_s[p], upd1W[(size_t)l * 261 * 128 + (256 + p) * 128 + tid], s);
        pc_s[tid] = s;
        b2u_s[tid] = upd2b[l * 128 + tid];
    }
    for (int i = tid; i < 128 * 32; i += 512) {  // f tile -> A_s
        int c = i >> 5, q = i & 31;
        ((float4*)(A_s + c * 132))[q] =
            ((const float4*)(g_f + (size_t)(n0 + c) * 128))[q];
    }
    for (int i = tid; i < 128 * 32; i += 512)    // upd1_W rows 0..127 (f part)
        ((float4*)W_s)[i] = ((const float4*)(upd1W + (size_t)l * 261 * 128))[i];
    __syncthreads();

    float acc2[4][8];
    ACC_ZERO(acc2);
    gemm128<32>(A_s, 132, W_s, 128, acc2, tr, tc);
    __syncthreads();
    for (int i = tid; i < 128 * 32; i += 512)    // upd1_W rows 128..255 (agg part)
        ((float4*)W_s)[i] =
            ((const float4*)(upd1W + (size_t)l * 261 * 128 + 128 * 128))[i];
    __syncthreads();
    gemm128<32>(M_s, 132, W_s, 128, acc2, tr, tc);
    __syncthreads();  // done reading M_s / W_s
#pragma unroll
    for (int i = 0; i < 4; ++i) {
        int c = tr + 32 * i;
#pragma unroll
        for (int j = 0; j < 8; ++j)
            M_s[c * 132 + tc * 8 + j] = swishf(acc2[i][j] + pc_s[tc * 8 + j]);
    }
    for (int i = tid; i < 128 * 32; i += 512)    // upd2_W
        ((float4*)W_s)[i] = ((const float4*)(upd2W + (size_t)l * 128 * 128))[i];
    __syncthreads();

    float acc3[4][8];
    ACC_ZERO(acc3);
    gemm128<32>(M_s, 132, W_s, 128, acc3, tr, tc);

    float val[4][8];
#pragma unroll
    for (int i = 0; i < 4; ++i) {
        int c = tr + 32 * i;
#pragma unroll
        for (int j = 0; j < 8; ++j)
            val[i][j] = A_s[c * 132 + tc * 8 + j] +
                        swishf(acc3[i][j] + b2u_s[tc * 8 + j]);
        float* gp = g_tmp + (size_t)(n0 + c) * 128 + tc * 8;
        ((float4*)gp)[0] = make_float4(val[i][0], val[i][1], val[i][2], val[i][3]);
        ((float4*)gp)[1] = make_float4(val[i][4], val[i][5], val[i][6], val[i][7]);
    }

    // -------- layernorm stats (sum, sumsq per (batch, channel)) --------
    __syncthreads();  // reuse M_s / A_s as reduction buffers
    float s1[8], s2[8];
#pragma unroll
    for (int j = 0; j < 8; ++j) { s1[j] = 0.0f; s2[j] = 0.0f; }
#pragma unroll
    for (int i = 0; i < 4; ++i)
#pragma unroll
        for (int j = 0; j < 8; ++j) {
            s1[j] += val[i][j];
            s2[j] += val[i][j] * val[i][j];
        }
#pragma unroll
    for (int j = 0; j < 8; ++j) {
        M_s[tr * 132 + tc * 8 + j] = s1[j];
        A_s[tr * 132 + tc * 8 + j] = s2[j];
    }
    __syncthreads();
    if (tid < 128) {
        float S = 0.0f, S2 = 0.0f;
#pragma unroll 8
        for (int g = 0; g < 32; ++g) {
            S += M_s[g * 132 + tid];
            S2 += A_s[g * 132 + tid];
        }
        atomicAdd(&g_stats[b * 2 * HID + tid], S);
        atomicAdd(&g_stats[b * 2 * HID + HID + tid], S2);
    }
}

// ---------------- layernorm apply: f = (tmp - mean) * rsqrt(var + eps) ------
__global__ __launch_bounds__(256) void k_norm() {
    __shared__ float mean_s[HID], rstd_s[HID];
    int b = blockIdx.x >> 9;  // 512 blocks per batch
    if (threadIdx.x < 128) {
        float m = g_stats[b * 2 * HID + threadIdx.x] * (1.0f / (float)HW);
        float v = g_stats[b * 2 * HID + HID + threadIdx.x] * (1.0f / (float)HW) - m * m;
        mean_s[threadIdx.x] = m;
        rstd_s[threadIdx.x] = rsqrtf(v + EPSV);
    }
    __syncthreads();
    size_t base = (size_t)blockIdx.x * 1024;
#pragma unroll
    for (int k = 0; k < 4; ++k) {
        size_t i4 = base + threadIdx.x + k * 256;
        int j = ((int)(i4 & 31)) * 4;
        float4 v = ((const float4*)g_tmp)[i4];
        v.x = (v.x - mean_s[j + 0]) * rstd_s[j + 0];
        v.y = (v.y - mean_s[j + 1]) * rstd_s[j + 1];
        v.z = (v.z - mean_s[j + 2]) * rstd_s[j + 2];
        v.w = (v.w - mean_s[j + 3]) * rstd_s[j + 3];
        ((float4*)g_f)[i4] = v;
    }
}

// ---------------- output head: out = u + DT * (swish(f@W1+b1)@W2 + b2) ------
__global__ __launch_bounds__(256, 2) void k_out(
    const float* __restrict__ inp, const float* __restrict__ W1,
    const float* __restrict__ b1, const float* __restrict__ W2,
    const float* __restrict__ b2, float* __restrict__ out) {
    extern __shared__ float sm[];
    float* f_s = sm;                   // 128*132
    float* W1_s = f_s + 128 * 132;     // 128*64
    float* b1_s = W1_s + 128 * 64;     // 64
    float* W2_s = b1_s + 64;           // 64
    float* red_s = W2_s + 64;          // 128*8

    int tid = threadIdx.x;
    int n0 = blockIdx.x * 128;
    int b = n0 / HW;

    for (int i = tid; i < 128 * 32; i += 256) {
        int c = i >> 5, q = i & 31;
        ((float4*)(f_s + c * 132))[q] =
            ((const float4*)(g_f + (size_t)(n0 + c) * 128))[q];
    }
    for (int i = tid; i < 128 * 16; i += 256)
        ((float4*)W1_s)[i] = ((const float4*)W1)[i];
    if (tid < 64) { b1_s[tid] = b1[tid]; W2_s[tid] = W2[tid]; }
    __syncthreads();

    int tc = tid & 7, tr = tid >> 3;  // tr in [0,32)
    float acc[4][8];
    ACC_ZERO(acc);
    gemm128<32>(f_s, 132, W1_s, 64, acc, tr, tc);
#pragma unroll
    for (int i = 0; i < 4; ++i) {
        float p = 0.0f;
#pragma unroll
        for (int j = 0; j < 8; ++j)
            p += swishf(acc[i][j] + b1_s[tc * 8 + j]) * W2_s[tc * 8 + j];
        red_s[(tr + 32 * i) * 8 + tc] = p;
    }
    __syncthreads();
    if (tid < 128) {
        float d = b2[0];
#pragma unroll
        for (int t = 0; t < 8; ++t) d += red_s[tid * 8 + t];
        int n = n0 + tid;
        out[n] = inp[b * NCH * HW + (n - b * HW)] + DTV * d;
    }
}

// ---------------- host launcher ----------------
extern "C" void kernel_launch(void* const* d_in, const int* in_sizes, int n_in,
                              void* d_out, int out_size) {
    const float* inp   = (const float*)d_in[0];
    const float* cp    = (const float*)d_in[1];
    // d_in[2] = edge_index (unused; graph is a structured 8-neighborhood stencil)
    const float* embW1 = (const float*)d_in[3];
    const float* embb1 = (const float*)d_in[4];
    const float* embW2 = (const float*)d_in[5];
    const float* embb2 = (const float*)d_in[6];
    const float* msg1W = (const float*)d_in[7];
    const float* msg1b = (const float*)d_in[8];
    const float* msg2W = (const float*)d_in[9];
    const float* msg2b = (const float*)d_in[10];
    const float* upd1W = (const float*)d_in[11];
    const float* upd1b = (const float*)d_in[12];
    const float* upd2W = (const float*)d_in[13];
    const float* upd2b = (const float*)d_in[14];
    const float* outW1 = (const float*)d_in[15];
    const float* outb1 = (const float*)d_in[16];
    const float* outW2 = (const float*)d_in[17];
    const float* outb2 = (const float*)d_in[18];
    float* out = (float*)d_out;

    const size_t smE = (size_t)(64 * 8 + 8 * 128 + 128 + 64 * 132 + 128 * 128 + 128) * 4;
    const size_t smA = (size_t)(64 * 132 + 128 * 128 + 128) * 4;
    const size_t smEdge = (size_t)(2 * 128 * 132 + 128 * 128 + 8 * 128 + 5 * 128 + 8) * 4;
    const size_t smO = (size_t)(128 * 132 + 128 * 64 + 64 + 64 + 128 * 8) * 4;

    cudaFuncSetAttribute(k_embed, cudaFuncAttributeMaxDynamicSharedMemorySize, (int)smE);
    cudaFuncSetAttribute(k_msgA, cudaFuncAttributeMaxDynamicSharedMemorySize, (int)smA);
    cudaFuncSetAttribute(k_edge, cudaFuncAttributeMaxDynamicSharedMemorySize, (int)smEdge);
    cudaFuncSetAttribute(k_out, cudaFuncAttributeMaxDynamicSharedMemorySize, (int)smO);

    k_embed<<<NN / 64, 256, smE>>>(inp, cp, embW1, embb1, embW2, embb2);
    for (int l = 0; l < NL; ++l) {
        k_msgA<<<NN / 64, 256, smA>>>(cp, msg1W, msg1b, l);
        k_edge<<<NN / 128, 512, smEdge>>>(inp, cp, msg1W, msg2W, msg2b,
                                          upd1W, upd1b, upd2W, upd2b, l);
        k_norm<<<2048, 256>>>();
    }
    k_out<<<NN / 128, 256, smO>>>(inp, outW1, outb1, outW2, outb2, out);
}